// round 3
// baseline (speedup 1.0000x reference)
#include <cuda_runtime.h>
#include <cuda_bf16.h>
#include <cstdint>

#define NN   50000
#define EE   800000
#define HID  128
#define NG   64
#define ODIM 64

// padded K stride (halves): 136 -> 68 words == 4 (mod 32) => conflict-free frag LDS
#define KP   136

// ---------------- device scratch (no allocations allowed) ----------------
__device__ float g_lbuf[NN * HID];   // x @ Wl^T   (gets aggregated over edges)
__device__ float g_rbuf[NN * HID];   // x @ Wr^T + b (self term)
__device__ float g_feat[NN * HID];   // layer activations
__device__ int   g_deg[NN];
__device__ int   g_rowptr[NN + 1];
__device__ int   g_cursor[NN];
__device__ int   g_csr_src[EE];
__device__ __align__(16) unsigned short g_Bh[3][256 * KP]; // split-bf16 weights, [n][k] padded
__device__ __align__(16) unsigned short g_Bl[3][256 * KP];
__device__ float g_pooled[NG * HID];
__device__ float g_counts[NG];

// ---------------- small utility kernels ----------------
__global__ void k_zero() {
    int i = blockIdx.x * blockDim.x + threadIdx.x;
    if (i < NN) g_deg[i] = 0;
    if (i < NG * HID) g_pooled[i] = 0.f;
    if (i < NG) g_counts[i] = 0.f;
}

__global__ void k_hist(const int* __restrict__ dst) {
    int e = blockIdx.x * blockDim.x + threadIdx.x;
    if (e < EE) atomicAdd(&g_deg[dst[e]], 1);
}

__global__ void k_scan() {
    __shared__ int ssum[1024];
    int tid = threadIdx.x;
    const int CH = (NN + 1023) / 1024;
    int base = tid * CH;
    int s = 0;
    for (int i = 0; i < CH; i++) { int idx = base + i; if (idx < NN) s += g_deg[idx]; }
    ssum[tid] = s;
    __syncthreads();
    for (int off = 1; off < 1024; off <<= 1) {
        int v = (tid >= off) ? ssum[tid - off] : 0;
        __syncthreads();
        ssum[tid] += v;
        __syncthreads();
    }
    int run = (tid == 0) ? 0 : ssum[tid - 1];
    for (int i = 0; i < CH; i++) {
        int idx = base + i;
        if (idx < NN) { g_rowptr[idx] = run; run += g_deg[idx]; }
    }
    if (tid == 1023) g_rowptr[NN] = run;
}

__global__ void k_copy_cursor() {
    int i = blockIdx.x * blockDim.x + threadIdx.x;
    if (i < NN) g_cursor[i] = g_rowptr[i];
}

__global__ void k_bin(const int* __restrict__ src, const int* __restrict__ dst) {
    int e = blockIdx.x * blockDim.x + threadIdx.x;
    if (e < EE) {
        int p = atomicAdd(&g_cursor[dst[e]], 1);
        g_csr_src[p] = src[e];
    }
}

// ---------------- weight prep: fp32 -> split bf16 hi/lo, [n][KP] padded ----------------
// n 0..127 -> Wl row n ; n 128..255 -> Wr row n-128   (B "col-major k x n" == [n][k])
__global__ void k_prep_w(const float* __restrict__ W1l, const float* __restrict__ W1r,
                         const float* __restrict__ W2l, const float* __restrict__ W2r,
                         const float* __restrict__ W3l, const float* __restrict__ W3r) {
    int idx = blockIdx.x * blockDim.x + threadIdx.x;
    if (idx >= 3 * 256 * 128) return;
    int l = idx >> 15;
    int n = (idx >> 7) & 255;
    int k = idx & 127;
    const float* W;
    if (l == 0)      W = (n < 128) ? W1l : W1r;
    else if (l == 1) W = (n < 128) ? W2l : W2r;
    else             W = (n < 128) ? W3l : W3r;
    float w = W[(n & 127) * 128 + k];
    __nv_bfloat16 h = __float2bfloat16(w);
    float lo = w - __bfloat162float(h);
    g_Bh[l][n * KP + k] = __bfloat16_as_ushort(h);
    g_Bl[l][n * KP + k] = __bfloat16_as_ushort(__float2bfloat16(lo));
}

// ---------------- mma.sync bf16 helper ----------------
__device__ __forceinline__ void mma_bf16(float* c, const uint32_t* a, const uint32_t* b) {
    asm volatile(
        "mma.sync.aligned.m16n8k16.row.col.f32.bf16.bf16.f32 "
        "{%0,%1,%2,%3}, {%4,%5,%6,%7}, {%8,%9}, {%0,%1,%2,%3};"
        : "+f"(c[0]), "+f"(c[1]), "+f"(c[2]), "+f"(c[3])
        : "r"(a[0]), "r"(a[1]), "r"(a[2]), "r"(a[3]), "r"(b[0]), "r"(b[1]));
}

// ---------------- tensor-core GEMM:  [lbuf|rbuf] = A @ [Wl^T | Wr^T] (+bias on rbuf) ----------------
// CTA: 128 rows x 256 cols, K=128. 16 warps, warp tile 64x32.
// Split bf16, 3 passes: Ah*Bh + Al*Bh + Ah*Bl.
#define OFF_AH 0
#define OFF_AL (128 * KP)
#define OFF_BH (2 * 128 * KP)
#define OFF_BL (2 * 128 * KP + 256 * KP)
#define SMEM_HALVES (2 * 128 * KP + 2 * 256 * KP)   // 104448 halves = 208896 B

__global__ void __launch_bounds__(512) k_gemm_mma(const float* __restrict__ Aext, int asel,
                                                  int layer, const float* __restrict__ bias) {
    extern __shared__ unsigned short sm[];
    const float* __restrict__ A = (asel < 0) ? Aext : g_feat;
    int tid = threadIdx.x;
    int m0 = blockIdx.x * 128;

    // ---- load A tile (fp32) -> split bf16 hi/lo in smem; thread = (row, quarter of 32 cols)
    {
        int row = tid >> 2;
        int q   = tid & 3;
        int gr  = m0 + row;
        unsigned short* dh = sm + OFF_AH + row * KP + q * 32;
        unsigned short* dl = sm + OFF_AL + row * KP + q * 32;
        const float4* src = (const float4*)(A + (size_t)gr * HID + q * 32);
        #pragma unroll
        for (int u = 0; u < 4; u++) {          // 8 cols per iter
            float v[8];
            if (gr < NN) {
                float4 p0 = src[u * 2], p1 = src[u * 2 + 1];
                v[0] = p0.x; v[1] = p0.y; v[2] = p0.z; v[3] = p0.w;
                v[4] = p1.x; v[5] = p1.y; v[6] = p1.z; v[7] = p1.w;
            } else {
                #pragma unroll
                for (int j = 0; j < 8; j++) v[j] = 0.f;
            }
            uint32_t hw[4], lw[4];
            #pragma unroll
            for (int p = 0; p < 4; p++) {
                __nv_bfloat16 h0 = __float2bfloat16(v[2 * p]);
                __nv_bfloat16 h1 = __float2bfloat16(v[2 * p + 1]);
                float r0 = v[2 * p]     - __bfloat162float(h0);
                float r1 = v[2 * p + 1] - __bfloat162float(h1);
                hw[p] = (uint32_t)__bfloat16_as_ushort(h0) |
                        ((uint32_t)__bfloat16_as_ushort(h1) << 16);
                lw[p] = (uint32_t)__bfloat16_as_ushort(__float2bfloat16(r0)) |
                        ((uint32_t)__bfloat16_as_ushort(__float2bfloat16(r1)) << 16);
            }
            *(uint4*)(dh + u * 8) = make_uint4(hw[0], hw[1], hw[2], hw[3]);
            *(uint4*)(dl + u * 8) = make_uint4(lw[0], lw[1], lw[2], lw[3]);
        }
    }
    // ---- copy pre-packed weights into smem (hi + lo, 69632 B each)
    {
        const uint4* sh = (const uint4*)(g_Bh[layer]);
        const uint4* sl = (const uint4*)(g_Bl[layer]);
        uint4* dh = (uint4*)(sm + OFF_BH);
        uint4* dl = (uint4*)(sm + OFF_BL);
        const int NV = 256 * KP / 8;   // 4352 uint4
        for (int i = tid; i < NV; i += 512) { dh[i] = sh[i]; dl[i] = sl[i]; }
    }
    __syncthreads();

    int lane = tid & 31, wid = tid >> 5;
    int g = lane >> 2, t = lane & 3;
    int mbase = (wid & 1) * 64;
    int nbase = (wid >> 1) * 32;

    float acc[4][4][4];
    #pragma unroll
    for (int i = 0; i < 4; i++)
        #pragma unroll
        for (int j = 0; j < 4; j++)
            #pragma unroll
            for (int c = 0; c < 4; c++) acc[i][j][c] = 0.f;

    #pragma unroll
    for (int pass = 0; pass < 3; pass++) {
        const unsigned short* Ap = sm + ((pass == 1) ? OFF_AL : OFF_AH);
        const unsigned short* Bp = sm + ((pass == 2) ? OFF_BL : OFF_BH);
        #pragma unroll
        for (int ks = 0; ks < 8; ks++) {
            int k0 = ks * 16;
            uint32_t af[4][4], bf[4][2];
            #pragma unroll
            for (int mt = 0; mt < 4; mt++) {
                const unsigned short* p = Ap + (mbase + mt * 16 + g) * KP + k0 + 2 * t;
                af[mt][0] = *(const uint32_t*)p;
                af[mt][1] = *(const uint32_t*)(p + 8 * KP);
                af[mt][2] = *(const uint32_t*)(p + 8);
                af[mt][3] = *(const uint32_t*)(p + 8 * KP + 8);
            }
            #pragma unroll
            for (int nt = 0; nt < 4; nt++) {
                const unsigned short* p = Bp + (nbase + nt * 8 + g) * KP + k0 + 2 * t;
                bf[nt][0] = *(const uint32_t*)p;
                bf[nt][1] = *(const uint32_t*)(p + 8);
            }
            #pragma unroll
            for (int mt = 0; mt < 4; mt++)
                #pragma unroll
                for (int nt = 0; nt < 4; nt++)
                    mma_bf16(acc[mt][nt], af[mt], bf[nt]);
        }
    }

    // ---- epilogue: cols < 128 -> lbuf ; cols >= 128 -> rbuf + bias
    bool left = (nbase < 128);
    #pragma unroll
    for (int nt = 0; nt < 4; nt++) {
        int col = nbase + nt * 8 + 2 * t;
        float2 bv = make_float2(0.f, 0.f);
        if (!left) bv = *(const float2*)(bias + (col - 128));
        #pragma unroll
        for (int mt = 0; mt < 4; mt++) {
            int r0 = m0 + mbase + mt * 16 + g;
            int r1 = r0 + 8;
            if (left) {
                if (r0 < NN) *(float2*)(g_lbuf + (size_t)r0 * HID + col) =
                    make_float2(acc[mt][nt][0], acc[mt][nt][1]);
                if (r1 < NN) *(float2*)(g_lbuf + (size_t)r1 * HID + col) =
                    make_float2(acc[mt][nt][2], acc[mt][nt][3]);
            } else {
                int oc = col - 128;
                if (r0 < NN) *(float2*)(g_rbuf + (size_t)r0 * HID + oc) =
                    make_float2(acc[mt][nt][0] + bv.x, acc[mt][nt][1] + bv.y);
                if (r1 < NN) *(float2*)(g_rbuf + (size_t)r1 * HID + oc) =
                    make_float2(acc[mt][nt][2] + bv.x, acc[mt][nt][3] + bv.y);
            }
        }
    }
}

// ---------------- fused aggregate + self + relu ----------------
__global__ void k_agg2(int relu) {
    int w    = (blockIdx.x * blockDim.x + threadIdx.x) >> 5;
    int lane = threadIdx.x & 31;
    if (w >= NN) return;
    int beg = g_rowptr[w], end = g_rowptr[w + 1];
    float4 acc = *(const float4*)(g_rbuf + (size_t)w * HID + lane * 4);
    int e = beg;
    for (; e + 1 < end; e += 2) {
        int s0 = g_csr_src[e];
        int s1 = g_csr_src[e + 1];
        float4 v0 = *(const float4*)(g_lbuf + (size_t)s0 * HID + lane * 4);
        float4 v1 = *(const float4*)(g_lbuf + (size_t)s1 * HID + lane * 4);
        acc.x += v0.x + v1.x; acc.y += v0.y + v1.y;
        acc.z += v0.z + v1.z; acc.w += v0.w + v1.w;
    }
    if (e < end) {
        int s0 = g_csr_src[e];
        float4 v0 = *(const float4*)(g_lbuf + (size_t)s0 * HID + lane * 4);
        acc.x += v0.x; acc.y += v0.y; acc.z += v0.z; acc.w += v0.w;
    }
    if (relu) {
        acc.x = fmaxf(acc.x, 0.f); acc.y = fmaxf(acc.y, 0.f);
        acc.z = fmaxf(acc.z, 0.f); acc.w = fmaxf(acc.w, 0.f);
    }
    *(float4*)(g_feat + (size_t)w * HID + lane * 4) = acc;
}

// ---------------- global mean pool ----------------
__global__ void k_pool(const int* __restrict__ batch) {
    const float* __restrict__ h = g_feat;
    const int NPW = 16;
    int w    = (blockIdx.x * blockDim.x + threadIdx.x) >> 5;
    int lane = threadIdx.x & 31;
    int n0 = w * NPW;
    if (n0 >= NN) return;
    int n1 = min(n0 + NPW, NN);
    float4 acc = make_float4(0.f, 0.f, 0.f, 0.f);
    int cg = -1, cnt = 0;
    for (int n = n0; n < n1; n++) {
        int g = batch[n];
        if (g != cg) {
            if (cg >= 0) {
                float* p = g_pooled + cg * HID + lane * 4;
                atomicAdd(p + 0, acc.x); atomicAdd(p + 1, acc.y);
                atomicAdd(p + 2, acc.z); atomicAdd(p + 3, acc.w);
                if (lane == 0) atomicAdd(&g_counts[cg], (float)cnt);
            }
            cg = g; acc = make_float4(0.f, 0.f, 0.f, 0.f); cnt = 0;
        }
        float4 v = *(const float4*)(h + (size_t)n * HID + lane * 4);
        acc.x += v.x; acc.y += v.y; acc.z += v.z; acc.w += v.w;
        cnt++;
    }
    if (cg >= 0) {
        float* p = g_pooled + cg * HID + lane * 4;
        atomicAdd(p + 0, acc.x); atomicAdd(p + 1, acc.y);
        atomicAdd(p + 2, acc.z); atomicAdd(p + 3, acc.w);
        if (lane == 0) atomicAdd(&g_counts[cg], (float)cnt);
    }
}

// ---------------- final linear ----------------
__global__ void k_final(const float* __restrict__ Wlin,
                        const float* __restrict__ blin,
                        float* __restrict__ out) {
    __shared__ float p[HID];
    int g = blockIdx.x, o = threadIdx.x;
    p[o]      = g_pooled[g * HID + o];
    p[o + 64] = g_pooled[g * HID + o + 64];
    __syncthreads();
    float inv = 1.f / fmaxf(g_counts[g], 1.f);
    float s = 0.f;
#pragma unroll
    for (int k = 0; k < HID; k++) s = fmaf(p[k], Wlin[o * HID + k], s);
    out[g * ODIM + o] = s * inv + blin[o];
}

// ---------------- launch ----------------
extern "C" void kernel_launch(void* const* d_in, const int* in_sizes, int n_in,
                              void* d_out, int out_size) {
    const float* x    = (const float*)d_in[0];
    const int*   ei   = (const int*)d_in[1];
    const int*   batch= (const int*)d_in[2];
    const float* W1l  = (const float*)d_in[3];
    const float* b1l  = (const float*)d_in[4];
    const float* W1r  = (const float*)d_in[5];
    const float* W2l  = (const float*)d_in[6];
    const float* b2l  = (const float*)d_in[7];
    const float* W2r  = (const float*)d_in[8];
    const float* W3l  = (const float*)d_in[9];
    const float* b3l  = (const float*)d_in[10];
    const float* W3r  = (const float*)d_in[11];
    const float* Wlin = (const float*)d_in[12];
    const float* blin = (const float*)d_in[13];
    float* out = (float*)d_out;

    const int* src = ei;
    const int* dst = ei + EE;

    const int SMEM_BYTES = SMEM_HALVES * 2;  // 208896
    cudaFuncSetAttribute(k_gemm_mma, cudaFuncAttributeMaxDynamicSharedMemorySize, SMEM_BYTES);

    const int ZB = (NN + 255) / 256;
    const int EB = (EE + 255) / 256;

    k_zero<<<ZB, 256>>>();
    k_hist<<<EB, 256>>>(dst);
    k_scan<<<1, 1024>>>();
    k_copy_cursor<<<ZB, 256>>>();
    k_bin<<<EB, 256>>>(src, dst);
    k_prep_w<<<384, 256>>>(W1l, W1r, W2l, W2r, W3l, W3r);

    const int GEMM_B = (NN + 127) / 128;       // 391
    const int AGG_B  = (NN * 32 + 255) / 256;

    k_gemm_mma<<<GEMM_B, 512, SMEM_BYTES>>>(x, -1, 0, b1l);
    k_agg2<<<AGG_B, 256>>>(1);
    k_gemm_mma<<<GEMM_B, 512, SMEM_BYTES>>>(nullptr, 0, 1, b2l);
    k_agg2<<<AGG_B, 256>>>(1);
    k_gemm_mma<<<GEMM_B, 512, SMEM_BYTES>>>(nullptr, 0, 2, b3l);
    k_agg2<<<AGG_B, 256>>>(0);

    const int POOL_W = (NN + 15) / 16;
    const int POOL_B = (POOL_W * 32 + 255) / 256;
    k_pool<<<POOL_B, 256>>>(batch);
    k_final<<<NG, ODIM>>>(Wlin, blin, out);
}

// round 4
// speedup vs baseline: 3.8258x; 3.8258x over previous
#include <cuda_runtime.h>
#include <cstdint>

#define NN   50000
#define EE   800000
#define HID  128
#define NG   64
#define ODIM 64

// ---------------- device scratch (no allocations allowed) ----------------
__device__ float g_lbuf[NN * HID];   // x @ Wl^T (aggregated over edges)
__device__ float g_rbuf[NN * HID];   // x @ Wr^T + b (self term)
__device__ float g_feat[NN * HID];   // layer activations
__device__ int   g_deg[NN];
__device__ int   g_rowptr[NN + 1];
__device__ int   g_cursor[NN];
__device__ int   g_csr_src[EE];
__device__ float g_WT[4][HID * HID]; // transposed weights [in][out]: W1l,W1r,W2l,W2r
__device__ float g_Pagg [NG * HID];  // sum over edges of h2[src], binned by batch[dst]
__device__ float g_Pself[NG * HID];  // sum over nodes of h2[n], binned by batch[n]
__device__ float g_cnt[NG];

// ---------------- init ----------------
__global__ void k_zero() {
    int i = blockIdx.x * blockDim.x + threadIdx.x;
    if (i < NN) g_deg[i] = 0;
    if (i < NG * HID) { g_Pagg[i] = 0.f; g_Pself[i] = 0.f; }
    if (i < NG) g_cnt[i] = 0.f;
}

__global__ void k_hist(const int* __restrict__ dst) {
    int e = blockIdx.x * blockDim.x + threadIdx.x;
    if (e < EE) atomicAdd(&g_deg[dst[e]], 1);
}

// single-block exclusive scan of g_deg -> g_rowptr AND g_cursor
__global__ void k_scan() {
    __shared__ int ssum[1024];
    int tid = threadIdx.x;
    const int CH = (NN + 1023) / 1024;
    int base = tid * CH;
    int s = 0;
    for (int i = 0; i < CH; i++) { int idx = base + i; if (idx < NN) s += g_deg[idx]; }
    ssum[tid] = s;
    __syncthreads();
    for (int off = 1; off < 1024; off <<= 1) {
        int v = (tid >= off) ? ssum[tid - off] : 0;
        __syncthreads();
        ssum[tid] += v;
        __syncthreads();
    }
    int run = (tid == 0) ? 0 : ssum[tid - 1];
    for (int i = 0; i < CH; i++) {
        int idx = base + i;
        if (idx < NN) { g_rowptr[idx] = run; g_cursor[idx] = run; run += g_deg[idx]; }
    }
    if (tid == 1023) g_rowptr[NN] = run;
}

__global__ void k_bin(const int* __restrict__ src, const int* __restrict__ dst) {
    int e = blockIdx.x * blockDim.x + threadIdx.x;
    if (e < EE) {
        int p = atomicAdd(&g_cursor[dst[e]], 1);
        g_csr_src[p] = src[e];
    }
}

// all 4 layer-1/2 weight transposes in one launch: W[o][k] -> g_WT[idx][k][o]
__global__ void k_transpose4(const float* __restrict__ W1l, const float* __restrict__ W1r,
                             const float* __restrict__ W2l, const float* __restrict__ W2r) {
    int i = blockIdx.x * blockDim.x + threadIdx.x;
    if (i >= 4 * HID * HID) return;
    int idx = i >> 14;
    int r = i & (HID * HID - 1);
    int o = r / HID, k = r % HID;
    const float* W = (idx == 0) ? W1l : (idx == 1) ? W1r : (idx == 2) ? W2l : W2r;
    g_WT[idx][k * HID + o] = W[o * HID + k];
}

// ---------------- fp32 SIMT GEMM: C = A @ WT (+bias if half==1) ----------------
// M=NN, N=128 per half, K=128. Block tile 128x128, 256 threads, 8x8/thread.
// blockIdx.y: 0 -> g_lbuf (Wl, no bias), 1 -> g_rbuf (Wr, +bias)
__global__ __launch_bounds__(256) void k_gemm(
    const float* __restrict__ Aext, int asel,
    int wbase,                      // WT index base: layer*2
    const float* __restrict__ bias)
{
    const float* __restrict__ A = (asel < 0) ? Aext : g_feat;
    int half = blockIdx.y;
    float* __restrict__ C = half ? g_rbuf : g_lbuf;
    const float* __restrict__ BT = g_WT[wbase + half];

    __shared__ float As[16][128];
    __shared__ float Bs[16][128];

    int tid = threadIdx.x;
    int tx = tid & 15;
    int ty = tid >> 4;
    int m0 = blockIdx.x * 128;

    float acc[8][8];
#pragma unroll
    for (int i = 0; i < 8; i++)
#pragma unroll
        for (int j = 0; j < 8; j++) acc[i][j] = 0.f;

    int arow = tid & 127;
    int akq0 = tid >> 7;
    int bj   = (tid & 31) * 4;
    int bk0  = tid >> 5;

    for (int k0 = 0; k0 < 128; k0 += 16) {
#pragma unroll
        for (int p = 0; p < 2; p++) {
            int kq = akq0 + p * 2;
            int grow = m0 + arow;
            float4 v = make_float4(0.f, 0.f, 0.f, 0.f);
            if (grow < NN)
                v = *(const float4*)(A + (size_t)grow * HID + k0 + kq * 4);
            As[kq * 4 + 0][arow] = v.x;
            As[kq * 4 + 1][arow] = v.y;
            As[kq * 4 + 2][arow] = v.z;
            As[kq * 4 + 3][arow] = v.w;
        }
#pragma unroll
        for (int p = 0; p < 2; p++) {
            int kr = bk0 + p * 8;
            *(float4*)&Bs[kr][bj] = *(const float4*)(BT + (size_t)(k0 + kr) * HID + bj);
        }
        __syncthreads();
#pragma unroll
        for (int kk = 0; kk < 16; kk++) {
            float a[8], b[8];
            *(float4*)&a[0] = *(const float4*)&As[kk][ty * 8];
            *(float4*)&a[4] = *(const float4*)&As[kk][ty * 8 + 4];
            *(float4*)&b[0] = *(const float4*)&Bs[kk][tx * 4];
            *(float4*)&b[4] = *(const float4*)&Bs[kk][64 + tx * 4];
#pragma unroll
            for (int i = 0; i < 8; i++)
#pragma unroll
                for (int j = 0; j < 8; j++)
                    acc[i][j] = fmaf(a[i], b[j], acc[i][j]);
        }
        __syncthreads();
    }

    float bv0[4], bv1[4];
#pragma unroll
    for (int j = 0; j < 4; j++) {
        bv0[j] = half ? bias[tx * 4 + j] : 0.f;
        bv1[j] = half ? bias[64 + tx * 4 + j] : 0.f;
    }
#pragma unroll
    for (int i = 0; i < 8; i++) {
        int grow = m0 + ty * 8 + i;
        if (grow >= NN) continue;
        float4 v0, v1;
        v0.x = acc[i][0] + bv0[0]; v0.y = acc[i][1] + bv0[1];
        v0.z = acc[i][2] + bv0[2]; v0.w = acc[i][3] + bv0[3];
        v1.x = acc[i][4] + bv1[0]; v1.y = acc[i][5] + bv1[1];
        v1.z = acc[i][6] + bv1[2]; v1.w = acc[i][7] + bv1[3];
        *(float4*)(C + (size_t)grow * HID + tx * 4)      = v0;
        *(float4*)(C + (size_t)grow * HID + 64 + tx * 4) = v1;
    }
}

// ---------------- fused aggregate + self + relu: feat = relu(sum lbuf[src] + rbuf[w]) ----------------
__global__ void k_agg2() {
    int w    = (blockIdx.x * blockDim.x + threadIdx.x) >> 5;
    int lane = threadIdx.x & 31;
    if (w >= NN) return;
    int beg = g_rowptr[w], end = g_rowptr[w + 1];
    float4 acc = *(const float4*)(g_rbuf + (size_t)w * HID + lane * 4);
    int e = beg;
    for (; e + 1 < end; e += 2) {
        int s0 = g_csr_src[e];
        int s1 = g_csr_src[e + 1];
        float4 v0 = *(const float4*)(g_lbuf + (size_t)s0 * HID + lane * 4);
        float4 v1 = *(const float4*)(g_lbuf + (size_t)s1 * HID + lane * 4);
        acc.x += v0.x + v1.x; acc.y += v0.y + v1.y;
        acc.z += v0.z + v1.z; acc.w += v0.w + v1.w;
    }
    if (e < end) {
        int s0 = g_csr_src[e];
        float4 v0 = *(const float4*)(g_lbuf + (size_t)s0 * HID + lane * 4);
        acc.x += v0.x; acc.y += v0.y; acc.z += v0.z; acc.w += v0.w;
    }
    acc.x = fmaxf(acc.x, 0.f); acc.y = fmaxf(acc.y, 0.f);
    acc.z = fmaxf(acc.z, 0.f); acc.w = fmaxf(acc.w, 0.f);
    *(float4*)(g_feat + (size_t)w * HID + lane * 4) = acc;
}

// ---------------- layer-3 collapsed: per-graph sums of h2 (self) and gathered h2 (agg) ----------------
// warp handles NPW consecutive nodes; batch sorted => few graph transitions per warp.
__global__ void k_pool3(const int* __restrict__ batch) {
    const float* __restrict__ h = g_feat;   // h2
    const int NPW = 16;
    int w    = (blockIdx.x * blockDim.x + threadIdx.x) >> 5;
    int lane = threadIdx.x & 31;
    int n0 = w * NPW;
    if (n0 >= NN) return;
    int n1 = min(n0 + NPW, NN);

    float4 aS = make_float4(0.f, 0.f, 0.f, 0.f);   // self sum
    float4 aA = make_float4(0.f, 0.f, 0.f, 0.f);   // edge-gather sum
    int cg = -1, cnt = 0;
    for (int n = n0; n < n1; n++) {
        int g = batch[n];
        if (g != cg) {
            if (cg >= 0) {
                float* ps = g_Pself + cg * HID + lane * 4;
                float* pa = g_Pagg  + cg * HID + lane * 4;
                atomicAdd(ps + 0, aS.x); atomicAdd(ps + 1, aS.y);
                atomicAdd(ps + 2, aS.z); atomicAdd(ps + 3, aS.w);
                atomicAdd(pa + 0, aA.x); atomicAdd(pa + 1, aA.y);
                atomicAdd(pa + 2, aA.z); atomicAdd(pa + 3, aA.w);
                if (lane == 0) atomicAdd(&g_cnt[cg], (float)cnt);
            }
            cg = g; cnt = 0;
            aS = make_float4(0.f, 0.f, 0.f, 0.f);
            aA = make_float4(0.f, 0.f, 0.f, 0.f);
        }
        // self term
        float4 v = *(const float4*)(h + (size_t)n * HID + lane * 4);
        aS.x += v.x; aS.y += v.y; aS.z += v.z; aS.w += v.w;
        cnt++;
        // edge gather for this dst node
        int beg = g_rowptr[n], end = g_rowptr[n + 1];
        int e = beg;
        for (; e + 1 < end; e += 2) {
            int s0 = g_csr_src[e];
            int s1 = g_csr_src[e + 1];
            float4 u0 = *(const float4*)(h + (size_t)s0 * HID + lane * 4);
            float4 u1 = *(const float4*)(h + (size_t)s1 * HID + lane * 4);
            aA.x += u0.x + u1.x; aA.y += u0.y + u1.y;
            aA.z += u0.z + u1.z; aA.w += u0.w + u1.w;
        }
        if (e < end) {
            int s0 = g_csr_src[e];
            float4 u0 = *(const float4*)(h + (size_t)s0 * HID + lane * 4);
            aA.x += u0.x; aA.y += u0.y; aA.z += u0.z; aA.w += u0.w;
        }
    }
    if (cg >= 0) {
        float* ps = g_Pself + cg * HID + lane * 4;
        float* pa = g_Pagg  + cg * HID + lane * 4;
        atomicAdd(ps + 0, aS.x); atomicAdd(ps + 1, aS.y);
        atomicAdd(ps + 2, aS.z); atomicAdd(ps + 3, aS.w);
        atomicAdd(pa + 0, aA.x); atomicAdd(pa + 1, aA.y);
        atomicAdd(pa + 2, aA.z); atomicAdd(pa + 3, aA.w);
        if (lane == 0) atomicAdd(&g_cnt[cg], (float)cnt);
    }
}

// ---------------- final: pooled = (Pagg@W3l^T + cnt*b3l + Pself@W3r^T)/cnt ; out = pooled@Wlin^T + blin
__global__ void k_final3(const float* __restrict__ W3l, const float* __restrict__ b3l,
                         const float* __restrict__ W3r,
                         const float* __restrict__ Wlin, const float* __restrict__ blin,
                         float* __restrict__ out) {
    __shared__ float sA[HID], sS[HID], sP[HID];
    int g = blockIdx.x, t = threadIdx.x;   // 64 blocks x 128 threads
    sA[t] = g_Pagg [g * HID + t];
    sS[t] = g_Pself[g * HID + t];
    __syncthreads();
    float cnt = g_cnt[g];
    float inv = 1.f / fmaxf(cnt, 1.f);
    float s = cnt * b3l[t];
    const float* wl = W3l + t * HID;
    const float* wr = W3r + t * HID;
#pragma unroll
    for (int k = 0; k < HID; k++) s = fmaf(sA[k], wl[k], fmaf(sS[k], wr[k], s));
    sP[t] = s * inv;
    __syncthreads();
    if (t < ODIM) {
        float o = blin[t];
        const float* wf = Wlin + t * HID;
#pragma unroll
        for (int k = 0; k < HID; k++) o = fmaf(sP[k], wf[k], o);
        out[g * ODIM + t] = o;
    }
}

// ---------------- launch ----------------
extern "C" void kernel_launch(void* const* d_in, const int* in_sizes, int n_in,
                              void* d_out, int out_size) {
    const float* x    = (const float*)d_in[0];
    const int*   ei   = (const int*)d_in[1];
    const int*   batch= (const int*)d_in[2];
    const float* W1l  = (const float*)d_in[3];
    const float* b1l  = (const float*)d_in[4];
    const float* W1r  = (const float*)d_in[5];
    const float* W2l  = (const float*)d_in[6];
    const float* b2l  = (const float*)d_in[7];
    const float* W2r  = (const float*)d_in[8];
    const float* W3l  = (const float*)d_in[9];
    const float* b3l  = (const float*)d_in[10];
    const float* W3r  = (const float*)d_in[11];
    const float* Wlin = (const float*)d_in[12];
    const float* blin = (const float*)d_in[13];
    float* out = (float*)d_out;

    const int* src = ei;
    const int* dst = ei + EE;

    const int ZB = (NN + 255) / 256;
    const int EB = (EE + 255) / 256;

    k_zero<<<ZB, 256>>>();
    k_hist<<<EB, 256>>>(dst);
    k_scan<<<1, 1024>>>();
    k_bin<<<EB, 256>>>(src, dst);
    k_transpose4<<<256, 256>>>(W1l, W1r, W2l, W2r);

    dim3 gemm_grid((NN + 127) / 128, 2);               // 391 x 2
    const int AGG_B = (NN * 32 + 255) / 256;

    // layer 1
    k_gemm<<<gemm_grid, 256>>>(x, -1, 0, b1l);
    k_agg2<<<AGG_B, 256>>>();
    // layer 2
    k_gemm<<<gemm_grid, 256>>>(nullptr, 0, 2, b2l);
    k_agg2<<<AGG_B, 256>>>();
    // layer 3 collapsed into per-graph reduction
    const int POOL_W = (NN + 15) / 16;
    const int POOL_B = (POOL_W * 32 + 255) / 256;
    k_pool3<<<POOL_B, 256>>>(batch);
    k_final3<<<NG, HID>>>(W3l, b3l, W3r, Wlin, blin, out);
}

// round 5
// speedup vs baseline: 3.8868x; 1.0160x over previous
#include <cuda_runtime.h>
#include <cstdint>

#define NN   50000
#define EE   800000
#define HID  128
#define NG   64
#define ODIM 64

// ---------------- device scratch (no allocations allowed) ----------------
__device__ float g_lbuf[NN * HID];   // x @ Wl^T (aggregated over edges)
__device__ float g_rbuf[NN * HID];   // x @ Wr^T + b (self term)
__device__ float g_feat[NN * HID];   // layer activations
__device__ int   g_deg[NN];
__device__ int   g_rowptr[NN + 1];
__device__ int   g_cursor[NN];
__device__ int   g_csr_src[EE];
__device__ float g_WT[4][HID * HID]; // transposed weights [in][out]: W1l,W1r,W2l,W2r
__device__ float g_Pagg [NG * HID];  // sum over edges of h2[src], binned by batch[dst]
__device__ float g_Pself[NG * HID];  // sum over nodes of h2[n], binned by batch[n]
__device__ float g_cnt[NG];

// ---------------- packed f32x2 helpers (Blackwell FFMA2 path) ----------------
__device__ __forceinline__ uint64_t splat2(float v) {
    uint64_t r;
    asm("mov.b64 %0, {%1, %1};" : "=l"(r) : "f"(v));
    return r;
}
__device__ __forceinline__ uint64_t pk2(float x, float y) {
    uint64_t r;
    asm("mov.b64 %0, {%1, %2};" : "=l"(r) : "f"(x), "f"(y));
    return r;
}
__device__ __forceinline__ void ffma2(uint64_t& d, uint64_t a, uint64_t b) {
    asm("fma.rn.f32x2 %0, %1, %2, %0;" : "+l"(d) : "l"(a), "l"(b));
}
__device__ __forceinline__ float2 unpk2(uint64_t v) {
    float x, y;
    asm("mov.b64 {%0, %1}, %2;" : "=f"(x), "=f"(y) : "l"(v));
    return make_float2(x, y);
}

// ---------------- init ----------------
__global__ void k_zero() {
    int i = blockIdx.x * blockDim.x + threadIdx.x;
    if (i < NN) g_deg[i] = 0;
    if (i < NG * HID) { g_Pagg[i] = 0.f; g_Pself[i] = 0.f; }
    if (i < NG) g_cnt[i] = 0.f;
}

__global__ void k_hist(const int* __restrict__ dst) {
    int e = blockIdx.x * blockDim.x + threadIdx.x;
    if (e < EE) atomicAdd(&g_deg[dst[e]], 1);
}

// single-block exclusive scan of g_deg -> g_rowptr AND g_cursor
__global__ void k_scan() {
    __shared__ int ssum[1024];
    int tid = threadIdx.x;
    const int CH = (NN + 1023) / 1024;
    int base = tid * CH;
    int s = 0;
    for (int i = 0; i < CH; i++) { int idx = base + i; if (idx < NN) s += g_deg[idx]; }
    ssum[tid] = s;
    __syncthreads();
    for (int off = 1; off < 1024; off <<= 1) {
        int v = (tid >= off) ? ssum[tid - off] : 0;
        __syncthreads();
        ssum[tid] += v;
        __syncthreads();
    }
    int run = (tid == 0) ? 0 : ssum[tid - 1];
    for (int i = 0; i < CH; i++) {
        int idx = base + i;
        if (idx < NN) { g_rowptr[idx] = run; g_cursor[idx] = run; run += g_deg[idx]; }
    }
    if (tid == 1023) g_rowptr[NN] = run;
}

__global__ void k_bin(const int* __restrict__ src, const int* __restrict__ dst) {
    int e = blockIdx.x * blockDim.x + threadIdx.x;
    if (e < EE) {
        int p = atomicAdd(&g_cursor[dst[e]], 1);
        g_csr_src[p] = src[e];
    }
}

// all 4 layer-1/2 weight transposes in one launch: W[o][k] -> g_WT[idx][k][o]
__global__ void k_transpose4(const float* __restrict__ W1l, const float* __restrict__ W1r,
                             const float* __restrict__ W2l, const float* __restrict__ W2r) {
    int i = blockIdx.x * blockDim.x + threadIdx.x;
    if (i >= 4 * HID * HID) return;
    int idx = i >> 14;
    int r = i & (HID * HID - 1);
    int o = r / HID, k = r % HID;
    const float* W = (idx == 0) ? W1l : (idx == 1) ? W1r : (idx == 2) ? W2l : W2r;
    g_WT[idx][k * HID + o] = W[o * HID + k];
}

// ---------------- fp32 GEMM with packed FFMA2: C = A @ WT (+bias if half==1) ----------------
// M=NN, N=128 per half, K=128. Block tile 128x128, 256 threads, 8x8/thread.
// blockIdx.y: 0 -> g_lbuf (Wl, no bias), 1 -> g_rbuf (Wr, +bias)
__global__ __launch_bounds__(256) void k_gemm(
    const float* __restrict__ Aext, int asel,
    int wbase, const float* __restrict__ bias)
{
    const float* __restrict__ A = (asel < 0) ? Aext : g_feat;
    int half = blockIdx.y;
    float* __restrict__ C = half ? g_rbuf : g_lbuf;
    const float* __restrict__ BT = g_WT[wbase + half];

    __shared__ float As[16][128];
    __shared__ float Bs[16][128];

    int tid = threadIdx.x;
    int tx = tid & 15;
    int ty = tid >> 4;
    int m0 = blockIdx.x * 128;

    // packed accumulators: acc[i][j] = cols {pair j} for row i
    // j=0: tx*4+0,1  j=1: tx*4+2,3  j=2: 64+tx*4+0,1  j=3: 64+tx*4+2,3
    uint64_t acc[8][4];
    uint64_t z = splat2(0.f);
#pragma unroll
    for (int i = 0; i < 8; i++)
#pragma unroll
        for (int j = 0; j < 4; j++) acc[i][j] = z;

    int arow = tid & 127;
    int akq0 = tid >> 7;
    int bj   = (tid & 31) * 4;
    int bk0  = tid >> 5;

    for (int k0 = 0; k0 < 128; k0 += 16) {
#pragma unroll
        for (int p = 0; p < 2; p++) {
            int kq = akq0 + p * 2;
            int grow = m0 + arow;
            float4 v = make_float4(0.f, 0.f, 0.f, 0.f);
            if (grow < NN)
                v = *(const float4*)(A + (size_t)grow * HID + k0 + kq * 4);
            As[kq * 4 + 0][arow] = v.x;
            As[kq * 4 + 1][arow] = v.y;
            As[kq * 4 + 2][arow] = v.z;
            As[kq * 4 + 3][arow] = v.w;
        }
#pragma unroll
        for (int p = 0; p < 2; p++) {
            int kr = bk0 + p * 8;
            *(float4*)&Bs[kr][bj] = *(const float4*)(BT + (size_t)(k0 + kr) * HID + bj);
        }
        __syncthreads();
#pragma unroll
        for (int kk = 0; kk < 16; kk++) {
            float a[8];
            *(float4*)&a[0] = *(const float4*)&As[kk][ty * 8];
            *(float4*)&a[4] = *(const float4*)&As[kk][ty * 8 + 4];
            float4 bl = *(const float4*)&Bs[kk][tx * 4];
            float4 bh = *(const float4*)&Bs[kk][64 + tx * 4];
            uint64_t bp[4];
            bp[0] = pk2(bl.x, bl.y); bp[1] = pk2(bl.z, bl.w);
            bp[2] = pk2(bh.x, bh.y); bp[3] = pk2(bh.z, bh.w);
#pragma unroll
            for (int i = 0; i < 8; i++) {
                uint64_t as_ = splat2(a[i]);
                ffma2(acc[i][0], as_, bp[0]);
                ffma2(acc[i][1], as_, bp[1]);
                ffma2(acc[i][2], as_, bp[2]);
                ffma2(acc[i][3], as_, bp[3]);
            }
        }
        __syncthreads();
    }

    float bv0[4], bv1[4];
#pragma unroll
    for (int j = 0; j < 4; j++) {
        bv0[j] = half ? bias[tx * 4 + j] : 0.f;
        bv1[j] = half ? bias[64 + tx * 4 + j] : 0.f;
    }
#pragma unroll
    for (int i = 0; i < 8; i++) {
        int grow = m0 + ty * 8 + i;
        if (grow >= NN) continue;
        float2 p0 = unpk2(acc[i][0]), p1 = unpk2(acc[i][1]);
        float2 p2 = unpk2(acc[i][2]), p3 = unpk2(acc[i][3]);
        float4 v0, v1;
        v0.x = p0.x + bv0[0]; v0.y = p0.y + bv0[1];
        v0.z = p1.x + bv0[2]; v0.w = p1.y + bv0[3];
        v1.x = p2.x + bv1[0]; v1.y = p2.y + bv1[1];
        v1.z = p3.x + bv1[2]; v1.w = p3.y + bv1[3];
        *(float4*)(C + (size_t)grow * HID + tx * 4)      = v0;
        *(float4*)(C + (size_t)grow * HID + 64 + tx * 4) = v1;
    }
}

// ---------------- fused aggregate + self + relu: feat = relu(sum lbuf[src] + rbuf[w]) ----------------
__global__ void k_agg2() {
    int w    = (blockIdx.x * blockDim.x + threadIdx.x) >> 5;
    int lane = threadIdx.x & 31;
    if (w >= NN) return;
    int beg = g_rowptr[w], end = g_rowptr[w + 1];
    float4 acc = *(const float4*)(g_rbuf + (size_t)w * HID + lane * 4);
    int e = beg;
    for (; e + 1 < end; e += 2) {
        int s0 = g_csr_src[e];
        int s1 = g_csr_src[e + 1];
        float4 v0 = *(const float4*)(g_lbuf + (size_t)s0 * HID + lane * 4);
        float4 v1 = *(const float4*)(g_lbuf + (size_t)s1 * HID + lane * 4);
        acc.x += v0.x + v1.x; acc.y += v0.y + v1.y;
        acc.z += v0.z + v1.z; acc.w += v0.w + v1.w;
    }
    if (e < end) {
        int s0 = g_csr_src[e];
        float4 v0 = *(const float4*)(g_lbuf + (size_t)s0 * HID + lane * 4);
        acc.x += v0.x; acc.y += v0.y; acc.z += v0.z; acc.w += v0.w;
    }
    acc.x = fmaxf(acc.x, 0.f); acc.y = fmaxf(acc.y, 0.f);
    acc.z = fmaxf(acc.z, 0.f); acc.w = fmaxf(acc.w, 0.f);
    *(float4*)(g_feat + (size_t)w * HID + lane * 4) = acc;
}

// ---------------- layer-3 collapsed: per-graph sums of h2 (self) and gathered h2 (agg) ----------------
__global__ void k_pool3(const int* __restrict__ batch) {
    const float* __restrict__ h = g_feat;
    const int NPW = 16;
    int w    = (blockIdx.x * blockDim.x + threadIdx.x) >> 5;
    int lane = threadIdx.x & 31;
    int n0 = w * NPW;
    if (n0 >= NN) return;
    int n1 = min(n0 + NPW, NN);

    float4 aS = make_float4(0.f, 0.f, 0.f, 0.f);
    float4 aA = make_float4(0.f, 0.f, 0.f, 0.f);
    int cg = -1, cnt = 0;
    for (int n = n0; n < n1; n++) {
        int g = batch[n];
        if (g != cg) {
            if (cg >= 0) {
                float* ps = g_Pself + cg * HID + lane * 4;
                float* pa = g_Pagg  + cg * HID + lane * 4;
                atomicAdd(ps + 0, aS.x); atomicAdd(ps + 1, aS.y);
                atomicAdd(ps + 2, aS.z); atomicAdd(ps + 3, aS.w);
                atomicAdd(pa + 0, aA.x); atomicAdd(pa + 1, aA.y);
                atomicAdd(pa + 2, aA.z); atomicAdd(pa + 3, aA.w);
                if (lane == 0) atomicAdd(&g_cnt[cg], (float)cnt);
            }
            cg = g; cnt = 0;
            aS = make_float4(0.f, 0.f, 0.f, 0.f);
            aA = make_float4(0.f, 0.f, 0.f, 0.f);
        }
        float4 v = *(const float4*)(h + (size_t)n * HID + lane * 4);
        aS.x += v.x; aS.y += v.y; aS.z += v.z; aS.w += v.w;
        cnt++;
        int beg = g_rowptr[n], end = g_rowptr[n + 1];
        int e = beg;
        for (; e + 1 < end; e += 2) {
            int s0 = g_csr_src[e];
            int s1 = g_csr_src[e + 1];
            float4 u0 = *(const float4*)(h + (size_t)s0 * HID + lane * 4);
            float4 u1 = *(const float4*)(h + (size_t)s1 * HID + lane * 4);
            aA.x += u0.x + u1.x; aA.y += u0.y + u1.y;
            aA.z += u0.z + u1.z; aA.w += u0.w + u1.w;
        }
        if (e < end) {
            int s0 = g_csr_src[e];
            float4 u0 = *(const float4*)(h + (size_t)s0 * HID + lane * 4);
            aA.x += u0.x; aA.y += u0.y; aA.z += u0.z; aA.w += u0.w;
        }
    }
    if (cg >= 0) {
        float* ps = g_Pself + cg * HID + lane * 4;
        float* pa = g_Pagg  + cg * HID + lane * 4;
        atomicAdd(ps + 0, aS.x); atomicAdd(ps + 1, aS.y);
        atomicAdd(ps + 2, aS.z); atomicAdd(ps + 3, aS.w);
        atomicAdd(pa + 0, aA.x); atomicAdd(pa + 1, aA.y);
        atomicAdd(pa + 2, aA.z); atomicAdd(pa + 3, aA.w);
        if (lane == 0) atomicAdd(&g_cnt[cg], (float)cnt);
    }
}

// ---------------- final: pooled = (Pagg@W3l^T + cnt*b3l + Pself@W3r^T)/cnt ; out = pooled@Wlin^T + blin
__global__ void k_final3(const float* __restrict__ W3l, const float* __restrict__ b3l,
                         const float* __restrict__ W3r,
                         const float* __restrict__ Wlin, const float* __restrict__ blin,
                         float* __restrict__ out) {
    __shared__ float sA[HID], sS[HID], sP[HID];
    int g = blockIdx.x, t = threadIdx.x;
    sA[t] = g_Pagg [g * HID + t];
    sS[t] = g_Pself[g * HID + t];
    __syncthreads();
    float cnt = g_cnt[g];
    float inv = 1.f / fmaxf(cnt, 1.f);
    float s = cnt * b3l[t];
    const float* wl = W3l + t * HID;
    const float* wr = W3r + t * HID;
#pragma unroll
    for (int k = 0; k < HID; k++) s = fmaf(sA[k], wl[k], fmaf(sS[k], wr[k], s));
    sP[t] = s * inv;
    __syncthreads();
    if (t < ODIM) {
        float o = blin[t];
        const float* wf = Wlin + t * HID;
#pragma unroll
        for (int k = 0; k < HID; k++) o = fmaf(sP[k], wf[k], o);
        out[g * ODIM + t] = o;
    }
}

// ---------------- launch ----------------
extern "C" void kernel_launch(void* const* d_in, const int* in_sizes, int n_in,
                              void* d_out, int out_size) {
    const float* x    = (const float*)d_in[0];
    const int*   ei   = (const int*)d_in[1];
    const int*   batch= (const int*)d_in[2];
    const float* W1l  = (const float*)d_in[3];
    const float* b1l  = (const float*)d_in[4];
    const float* W1r  = (const float*)d_in[5];
    const float* W2l  = (const float*)d_in[6];
    const float* b2l  = (const float*)d_in[7];
    const float* W2r  = (const float*)d_in[8];
    const float* W3l  = (const float*)d_in[9];
    const float* b3l  = (const float*)d_in[10];
    const float* W3r  = (const float*)d_in[11];
    const float* Wlin = (const float*)d_in[12];
    const float* blin = (const float*)d_in[13];
    float* out = (float*)d_out;

    const int* src = ei;
    const int* dst = ei + EE;

    const int ZB = (NN + 255) / 256;
    const int EB = (EE + 255) / 256;

    k_zero<<<ZB, 256>>>();
    k_hist<<<EB, 256>>>(dst);
    k_scan<<<1, 1024>>>();
    k_bin<<<EB, 256>>>(src, dst);
    k_transpose4<<<256, 256>>>(W1l, W1r, W2l, W2r);

    dim3 gemm_grid((NN + 127) / 128, 2);
    const int AGG_B = (NN * 32 + 255) / 256;

    k_gemm<<<gemm_grid, 256>>>(x, -1, 0, b1l);
    k_agg2<<<AGG_B, 256>>>();
    k_gemm<<<gemm_grid, 256>>>(nullptr, 0, 2, b2l);
    k_agg2<<<AGG_B, 256>>>();

    const int POOL_W = (NN + 15) / 16;
    const int POOL_B = (POOL_W * 32 + 255) / 256;
    k_pool3<<<POOL_B, 256>>>(batch);
    k_final3<<<NG, HID>>>(W3l, b3l, W3r, Wlin, blin, out);
}